// round 5
// baseline (speedup 1.0000x reference)
#include <cuda_runtime.h>
#include <math.h>

#define N_NODES   20000
#define N_EDGES   320000
#define NUM_GRAPHS 64
#define D0 256   // input dim
#define D1 256   // hidden 1
#define D2 128   // hidden 2

// ---------------- device scratch (static globals; no runtime alloc) ----------------
__device__ __align__(16) int   g_deg[N_NODES];
__device__ __align__(16) int   g_csr_off[N_NODES + 1];
__device__ __align__(16) int   g_csr_cur[N_NODES];
__device__ __align__(16) int   g_csr_src[N_EDGES];
__device__ __align__(16) float g_dinv[N_NODES];
__device__ __align__(16) float g_h1[(size_t)N_NODES * D1];   // X@W1
__device__ __align__(16) float g_z1[(size_t)N_NODES * D1];   // relu(agg1 + b1)
__device__ __align__(16) float g_h2[(size_t)N_NODES * D2];   // Z1@W2
__device__ __align__(16) float g_gsum[NUM_GRAPHS * D2];
__device__ __align__(16) int   g_gcnt[NUM_GRAPHS];

// ---------------- init: zero per-launch accumulators ----------------
__global__ void init_kernel() {
    int i = blockIdx.x * blockDim.x + threadIdx.x;
    int stride = gridDim.x * blockDim.x;
    for (int k = i; k < N_NODES; k += stride) g_deg[k] = 0;
    for (int k = i; k < NUM_GRAPHS * D2; k += stride) g_gsum[k] = 0.0f;
    if (i < NUM_GRAPHS) g_gcnt[i] = 0;
}

// ---------------- degree histogram over dst (edge_index is int32) ----------------
__global__ void count_kernel(const int* __restrict__ ei) {
    int e = blockIdx.x * blockDim.x + threadIdx.x;
    if (e < N_EDGES) atomicAdd(&g_deg[ei[N_EDGES + e]], 1);
}

// ---------------- single-block scan: csr_off (exclusive), csr_cur, dinv ----------------
__global__ void scan_kernel() {
    __shared__ int s[1024];
    int tid = threadIdx.x;
    int carry = 0;
    for (int base = 0; base < N_NODES; base += 1024) {
        int i = base + tid;
        int v = (i < N_NODES) ? g_deg[i] : 0;
        s[tid] = v;
        __syncthreads();
        for (int off = 1; off < 1024; off <<= 1) {
            int t2 = (tid >= off) ? s[tid - off] : 0;
            __syncthreads();
            s[tid] += t2;
            __syncthreads();
        }
        int incl = carry + s[tid];
        if (i < N_NODES) {
            g_csr_off[i + 1] = incl;
            g_csr_cur[i]     = incl - v;                  // exclusive offset
            g_dinv[i]        = rsqrtf((float)(v + 1));    // in-degree + self loop
        }
        if (i == 0) g_csr_off[0] = 0;
        int tot = s[1023];
        __syncthreads();
        carry += tot;
    }
}

// ---------------- CSR fill (grouped by dst) ----------------
__global__ void fill_kernel(const int* __restrict__ ei) {
    int e = blockIdx.x * blockDim.x + threadIdx.x;
    if (e < N_EDGES) {
        int d = ei[N_EDGES + e];
        int slot = atomicAdd(&g_csr_cur[d], 1);
        g_csr_src[slot] = ei[e];
    }
}

// ---------------- fp32 tiled GEMM: C[M,N] = A[M,K] @ B[K,N] ----------------
#define BM 64
#define BN 64
#define BK 32
__global__ void gemm_kernel(const float* __restrict__ A, const float* __restrict__ B,
                            float* __restrict__ C, int M, int N, int K) {
    __shared__ float As[BM][BK + 1];
    __shared__ float Bs[BK][BN + 4];
    int tid = threadIdx.x;            // 256 threads
    int tx = tid & 15, ty = tid >> 4; // 16x16
    int row0 = blockIdx.x * BM;
    int col0 = blockIdx.y * BN;

    float acc[4][4] = {};

    for (int k0 = 0; k0 < K; k0 += BK) {
        // load A tile: 64x32 = 512 float4
        #pragma unroll
        for (int i = 0; i < 2; i++) {
            int idx = tid + i * 256;
            int r = idx >> 3;
            int c4 = (idx & 7) * 4;
            float4 v = make_float4(0.f, 0.f, 0.f, 0.f);
            int gr = row0 + r;
            if (gr < M) v = *reinterpret_cast<const float4*>(&A[(size_t)gr * K + k0 + c4]);
            As[r][c4] = v.x; As[r][c4 + 1] = v.y; As[r][c4 + 2] = v.z; As[r][c4 + 3] = v.w;
        }
        // load B tile: 32x64 = 512 float4
        #pragma unroll
        for (int i = 0; i < 2; i++) {
            int idx = tid + i * 256;
            int r = idx >> 4;
            int c4 = (idx & 15) * 4;
            float4 v = *reinterpret_cast<const float4*>(&B[(size_t)(k0 + r) * N + col0 + c4]);
            Bs[r][c4] = v.x; Bs[r][c4 + 1] = v.y; Bs[r][c4 + 2] = v.z; Bs[r][c4 + 3] = v.w;
        }
        __syncthreads();
        #pragma unroll
        for (int kk = 0; kk < BK; kk++) {
            float a[4], b[4];
            #pragma unroll
            for (int i = 0; i < 4; i++) a[i] = As[ty * 4 + i][kk];
            #pragma unroll
            for (int j = 0; j < 4; j++) b[j] = Bs[kk][tx * 4 + j];
            #pragma unroll
            for (int i = 0; i < 4; i++)
                #pragma unroll
                for (int j = 0; j < 4; j++)
                    acc[i][j] = fmaf(a[i], b[j], acc[i][j]);
        }
        __syncthreads();
    }
    #pragma unroll
    for (int i = 0; i < 4; i++) {
        int gr = row0 + ty * 4 + i;
        if (gr < M) {
            #pragma unroll
            for (int j = 0; j < 4; j++)
                C[(size_t)gr * N + col0 + tx * 4 + j] = acc[i][j];
        }
    }
}

// ---------------- gather aggregation: out[d] = relu(dinv[d]*(dinv[d]*h[d] + sum dinv[s]*h[s]) + b) ----------------
template <int F, bool POOL>
__global__ void aggregate_kernel(const float* __restrict__ H, const float* __restrict__ bias,
                                 float* __restrict__ Z, const int* __restrict__ batch) {
    int node = blockIdx.x;
    int t = threadIdx.x;
    float di = g_dinv[node];
    float acc = di * __ldg(&H[(size_t)node * F + t]);
    int e0 = g_csr_off[node], e1 = g_csr_off[node + 1];
    for (int e = e0; e < e1; e++) {
        int s = g_csr_src[e];
        acc += g_dinv[s] * __ldg(&H[(size_t)s * F + t]);
    }
    float v = fmaxf(di * acc + bias[t], 0.0f);
    if (POOL) {
        int g = batch[node];
        atomicAdd(&g_gsum[g * F + t], v);
        if (t == 0) atomicAdd(&g_gcnt[g], 1);
    } else {
        Z[(size_t)node * F + t] = v;
    }
}

// ---------------- head MLP: mean-pool -> relu(g@Wl1+bl1) -> sigmoid(@Wl2+bl2) ----------------
__global__ void final_kernel(const float* __restrict__ Wl1, const float* __restrict__ bl1,
                             const float* __restrict__ Wl2, const float* __restrict__ bl2,
                             float* __restrict__ out) {
    int g = blockIdx.x;     // 64 graphs
    int j = threadIdx.x;    // 64 threads
    __shared__ float sg[D2];
    __shared__ float sr[64];
    float cnt = (float)max(g_gcnt[g], 1);
    for (int k = j; k < D2; k += 64) sg[k] = g_gsum[g * D2 + k] / cnt;
    __syncthreads();
    float acc = bl1[j];
    #pragma unroll 8
    for (int k = 0; k < D2; k++) acc = fmaf(sg[k], Wl1[k * 64 + j], acc);
    acc = fmaxf(acc, 0.0f);
    sr[j] = acc * Wl2[j];
    #pragma unroll
    for (int off = 32; off > 0; off >>= 1) {
        __syncthreads();
        if (j < off) sr[j] += sr[j + off];
    }
    __syncthreads();
    if (j == 0) out[g] = 1.0f / (1.0f + expf(-(sr[0] + bl2[0])));
}

// ---------------- launch ----------------
extern "C" void kernel_launch(void* const* d_in, const int* in_sizes, int n_in,
                              void* d_out, int out_size) {
    const float* x     = (const float*)d_in[0];
    const int*   ei    = (const int*)d_in[1];     // int32 (JAX x64 disabled)
    const int*   batch = (const int*)d_in[2];     // int32
    const float* W1  = (const float*)d_in[3];
    const float* b1  = (const float*)d_in[4];
    const float* W2  = (const float*)d_in[5];
    const float* b2  = (const float*)d_in[6];
    const float* Wl1 = (const float*)d_in[7];
    const float* bl1 = (const float*)d_in[8];
    const float* Wl2 = (const float*)d_in[9];
    const float* bl2 = (const float*)d_in[10];
    float* out = (float*)d_out;

    void* p;
    cudaGetSymbolAddress(&p, g_h1); float* h1 = (float*)p;
    cudaGetSymbolAddress(&p, g_z1); float* z1 = (float*)p;
    cudaGetSymbolAddress(&p, g_h2); float* h2 = (float*)p;

    init_kernel<<<64, 256>>>();
    count_kernel<<<(N_EDGES + 255) / 256, 256>>>(ei);
    scan_kernel<<<1, 1024>>>();
    fill_kernel<<<(N_EDGES + 255) / 256, 256>>>(ei);

    dim3 gg1((N_NODES + BM - 1) / BM, D1 / BN);
    gemm_kernel<<<gg1, 256>>>(x, W1, h1, N_NODES, D1, D0);
    aggregate_kernel<D1, false><<<N_NODES, D1>>>(h1, b1, z1, nullptr);

    dim3 gg2((N_NODES + BM - 1) / BM, D2 / BN);
    gemm_kernel<<<gg2, 256>>>(z1, W2, h2, N_NODES, D2, D1);
    aggregate_kernel<D2, true><<<N_NODES, D2>>>(h2, b2, nullptr, batch);

    final_kernel<<<NUM_GRAPHS, 64>>>(Wl1, bl1, Wl2, bl2, out);
}